// round 15
// baseline (speedup 1.0000x reference)
#include <cuda_runtime.h>

// SpatialDeformer3D via SMEM-tiled trilinear gather, v11:
//  - PERSISTENT work-stealing CTAs: 2 x SM_count resident CTAs pull tile
//    indices from a device counter (reset by a prologue kernel). Removes
//    the ~10% wave-quantization tail of the 1200-CTA static grid.
//  - per-tile body identical to v10 (77.9us): 16x16x32 tile, +/-2 halo,
//    batched fill, depth-2 def register pipeline, __ldcs def, __stcs out,
//    fast path = base + 8 immediate-offset LDS, rare fallback = exact
//    reference math with clamps + global gathers.
//
//   X:           (2, 160, 192, 160, 2)  float32
//   deformation: (2, 160, 192, 160, 3)  float32
//   out:         (2, 160, 192, 160, 1)  float32

#define BB 2
#define HH 160
#define WW 192
#define DD 160
#define WD (WW * DD)

#define TH 16
#define TW 16
#define TD 32
#define RLO 2              // halo below; +3 above (x1=x0+1) => extent T+5
#define HS (TH + 5)        // 21
#define WS (TW + 5)        // 21
#define DS (TD + 5)        // 37
#define NROWS (HS * WS)    // 441
#define SVOL (NROWS * DS)  // 16317 floats = 65268 B

#define NTHR 1024
#define NWARP (NTHR / 32)  // 32
#define FG 7               // fill group size (rows per warp per batch)

#define NTILE_D (DD / TD)                  // 5
#define NTILE_W (WW / TW)                  // 12
#define NTILE_H (HH / TH)                  // 10
#define NTILES (NTILE_D * NTILE_W * NTILE_H * BB)   // 1200

__device__ unsigned int g_tile_ctr;

__global__ void reset_ctr_kernel() { g_tile_ctr = 0u; }

__global__ __launch_bounds__(NTHR, 2) void deform3d_tile11_kernel(
    const float* __restrict__ X,
    const float* __restrict__ def,
    float* __restrict__ out)
{
    extern __shared__ float s[];
    __shared__ unsigned int s_tile;

    const int lane = threadIdx.x;          // 0..31 -> d
    const int ty   = threadIdx.y;          // 0..31
    const int wy   = ty & 15;              // -> w
    const int hg   = ty >> 4;              // 0/1 -> h half (8 planes each)
    const int warpId = ty;                 // 32 warps
    const int tid0 = (lane == 0) & (ty == 0);

    for (;;) {
        if (tid0) s_tile = atomicAdd(&g_tile_ctr, 1u);
        __syncthreads();                    // broadcast + protect smem reuse
        const unsigned int t = s_tile;
        if (t >= NTILES) break;

        // Decode tile (d fastest, matches old grid x-fastest linearization).
        const int td_ = t % NTILE_D;
        const unsigned int r1 = t / NTILE_D;
        const int tw_ = r1 % NTILE_W;
        const unsigned int r2 = r1 / NTILE_W;
        const int b  = r2 / NTILE_H;
        const int hz = r2 % NTILE_H;

        const int h0 = hz * TH;
        const int w0 = tw_ * TW;
        const int d0 = td_ * TD;

        const float* Xb = X + (size_t)b * (HH * WW * DD * 2);

        const int yb = h0 - RLO;
        const int xb = w0 - RLO;
        const int zb = d0 - RLO;

        const int d = d0 + lane;
        const int w = w0 + wy;
        const int hbase = h0 + hg * (TH / 2);

        const int vox0 = ((b * HH + hbase) * WW + w) * DD + d;

        // ---- Prologue: def loads for iterations 0, 1 issued first so the
        //      fill hides their DRAM latency. ----
        float bx0, by0, bz0, bx1, by1, bz1;
        {
            const float* dp0 = def + (size_t)vox0 * 3;
            const float* dp1 = dp0 + (size_t)WD * 3;
            bx0 = __ldcs(dp0 + 0); by0 = __ldcs(dp0 + 1); bz0 = __ldcs(dp0 + 2);
            bx1 = __ldcs(dp1 + 0); by1 = __ldcs(dp1 + 1); bz1 = __ldcs(dp1 + 2);
        }

        // ---- SMEM fill: one warp per (hy,wx) row; rows batched in groups
        //      of 7 so all group LDGs are outstanding before the first STS.
        {
            const int ezA = min(max(zb + lane, 0), DD - 1) * 2;
            const int ezB = min(max(zb + lane + 32, 0), DD - 1) * 2;

            int hy = warpId / WS;
            int wx = warpId - hy * WS;

            #pragma unroll
            for (int g = 0; g < 2; g++) {
                const int rbase = warpId + g * (NWARP * FG);
                float vA[FG], vB[FG];

                #pragma unroll
                for (int j = 0; j < FG; j++) {
                    int row = rbase + j * NWARP;
                    if (row < NROWS) {
                        int gy = min(max(yb + hy, 0), HH - 1);
                        int gx = min(max(xb + wx, 0), WW - 1);
                        const float* src =
                            Xb + (size_t)(gy * WW + gx) * (DD * 2);
                        vA[j] = __ldg(src + ezA);
                        vB[j] = (lane < DS - 32) ? __ldg(src + ezB) : 0.0f;
                        wx += NWARP;
                        while (wx >= WS) { wx -= WS; hy++; }
                    }
                }

                #pragma unroll
                for (int j = 0; j < FG; j++) {
                    int row = rbase + j * NWARP;
                    if (row < NROWS) {
                        float* dst = s + row * DS;
                        dst[lane] = vA[j];
                        if (lane < DS - 32)
                            dst[lane + 32] = vB[j];
                    }
                }
            }
        }
        __syncthreads();

        // Fast-path bounds: corner index c0 must satisfy clip-identity AND
        // in-tile:  c0 in [max(0, base), min(base + S - 2, LIM - 2)].
        const int loY = max(0, yb), rngY = min(yb + HS - 2, HH - 2) - loY;
        const int loX = max(0, xb), rngX = min(xb + WS - 2, WW - 2) - loX;
        const int loZ = max(0, zb), rngZ = min(zb + DS - 2, DD - 2) - loZ;

        const float wf = (float)w;
        const float df = (float)d;
        float hf = (float)hbase;

        int vox = vox0;
        const float* dpn = def + ((size_t)vox0 + (size_t)2 * WD) * 3;

        #pragma unroll
        for (int hh = 0; hh < TH / 2; hh++, vox += WD, hf += 1.0f) {
            // Consume the stage loaded 2 iterations ago.
            float dx, dy, dzv;
            if ((hh & 1) == 0) { dx = bx0; dy = by0; dzv = bz0; }
            else               { dx = bx1; dy = by1; dzv = bz1; }

            // Refill this stage with iteration hh+2.
            if (hh < TH / 2 - 2) {
                float nx = __ldcs(dpn + 0);
                float ny = __ldcs(dpn + 1);
                float nz = __ldcs(dpn + 2);
                if ((hh & 1) == 0) { bx0 = nx; by0 = ny; bz0 = nz; }
                else               { bx1 = nx; by1 = ny; bz1 = nz; }
                dpn += (size_t)WD * 3;
            }

            float x = wf + dx;          // def[...,0] -> W axis
            float y = hf + dy;          // def[...,1] -> H axis
            float z = df + dzv;         // def[...,2] -> D axis

            int x0 = __float2int_rd(x);
            int y0 = __float2int_rd(y);
            int z0 = __float2int_rd(z);

            bool fast = ((unsigned)(y0 - loY) <= (unsigned)rngY) &
                        ((unsigned)(x0 - loX) <= (unsigned)rngX) &
                        ((unsigned)(z0 - loZ) <= (unsigned)rngZ);

            float res;
            if (fast) {
                // clip == identity: x1 = x0+1 etc., all taps in SMEM tile.
                float x0f = (float)x0, y0f = (float)y0, z0f = (float)z0;
                float wx1 = x - x0f, wx0 = (x0f + 1.0f) - x;
                float wy1 = y - y0f, wy0 = (y0f + 1.0f) - y;
                float wz1 = z - z0f, wz0 = (z0f + 1.0f) - z;

                int base = ((y0 - yb) * WS + (x0 - xb)) * DS + (z0 - zb);

                float p000 = s[base];
                float p001 = s[base + 1];
                float p010 = s[base + DS];
                float p011 = s[base + DS + 1];
                float p100 = s[base + WS * DS];
                float p101 = s[base + WS * DS + 1];
                float p110 = s[base + WS * DS + DS];
                float p111 = s[base + WS * DS + DS + 1];

                res = wy0 * (wx0 * (wz0 * p000 + wz1 * p001) +
                             wx1 * (wz0 * p010 + wz1 * p011)) +
                      wy1 * (wx0 * (wz0 * p100 + wz1 * p101) +
                             wx1 * (wz0 * p110 + wz1 * p111));
            } else {
                // Exact reference path: clip each corner independently;
                // weights from CLIPPED coords so out-of-range dims cancel.
                int x1 = x0 + 1, y1 = y0 + 1, z1 = z0 + 1;
                x0 = min(max(x0, 0), WW - 1);  x1 = min(max(x1, 0), WW - 1);
                y0 = min(max(y0, 0), HH - 1);  y1 = min(max(y1, 0), HH - 1);
                z0 = min(max(z0, 0), DD - 1);  z1 = min(max(z1, 0), DD - 1);

                float wx0 = (float)x1 - x, wx1 = x - (float)x0;
                float wy0 = (float)y1 - y, wy1 = y - (float)y0;
                float wz0 = (float)z1 - z, wz1 = z - (float)z0;

                int i00 = (y0 * WW + x0) * (DD * 2);
                int i01 = (y0 * WW + x1) * (DD * 2);
                int i10 = (y1 * WW + x0) * (DD * 2);
                int i11 = (y1 * WW + x1) * (DD * 2);
                int z0e = z0 * 2, z1e = z1 * 2;
                float p000 = __ldg(Xb + i00 + z0e), p001 = __ldg(Xb + i00 + z1e);
                float p010 = __ldg(Xb + i01 + z0e), p011 = __ldg(Xb + i01 + z1e);
                float p100 = __ldg(Xb + i10 + z0e), p101 = __ldg(Xb + i10 + z1e);
                float p110 = __ldg(Xb + i11 + z0e), p111 = __ldg(Xb + i11 + z1e);

                res = wy0 * (wx0 * (wz0 * p000 + wz1 * p001) +
                             wx1 * (wz0 * p010 + wz1 * p011)) +
                      wy1 * (wx0 * (wz0 * p100 + wz1 * p101) +
                             wx1 * (wz0 * p110 + wz1 * p111));
            }

            __stcs(out + vox, res);   // streaming store: keep L2 for X reuse
        }
        // No trailing sync: next iteration's top __syncthreads protects smem.
    }
}

extern "C" void kernel_launch(void* const* d_in, const int* in_sizes, int n_in,
                              void* d_out, int out_size)
{
    const float* X   = (const float*)d_in[0];
    const float* def = (const float*)d_in[1];
    float* out = (float*)d_out;

    static int nsm = 0;
    if (nsm == 0) {
        cudaDeviceGetAttribute(&nsm, cudaDevAttrMultiProcessorCount, 0);
        if (nsm <= 0) nsm = 148;
        cudaFuncSetAttribute(deform3d_tile11_kernel,
                             cudaFuncAttributeMaxDynamicSharedMemorySize,
                             SVOL * (int)sizeof(float));
    }

    reset_ctr_kernel<<<1, 1>>>();

    int nblocks = 2 * nsm;                 // 2 resident CTAs per SM
    if (nblocks > NTILES) nblocks = NTILES;
    dim3 block(32, 32, 1);                 // 1024 threads
    deform3d_tile11_kernel<<<nblocks, block, SVOL * sizeof(float)>>>(X, def, out);
}

// round 16
// speedup vs baseline: 1.1879x; 1.1879x over previous
#include <cuda_runtime.h>

// SpatialDeformer3D via SMEM-tiled trilinear gather, v12:
//  - v10 core (static 1200-CTA grid, 16x16x32 tile, batched fill, depth-2
//    def pipeline, <=32 regs, 2 CTAs/SM)  [77.9us baseline]
//  - FALLBACK COMPACTION: non-fast lanes enqueue their voxel index into a
//    per-CTA SMEM queue (warp-aggregated atomic) instead of executing the
//    heavy clip+global-gather path inline. A post-pass drains the queue
//    with full warp efficiency using the exact reference math.
//
//   X:           (2, 160, 192, 160, 2)  float32
//   deformation: (2, 160, 192, 160, 3)  float32
//   out:         (2, 160, 192, 160, 1)  float32

#define BB 2
#define HH 160
#define WW 192
#define DD 160
#define WD (WW * DD)
#define NN (HH * WD)

#define TH 16
#define TW 16
#define TD 32
#define RLO 2              // halo below; +3 above (x1=x0+1) => extent T+5
#define HS (TH + 5)        // 21
#define WS (TW + 5)        // 21
#define DS (TD + 5)        // 37
#define NROWS (HS * WS)    // 441
#define SVOL (NROWS * DS)  // 16317 floats = 65268 B

#define QCAP (TH * TW * TD)            // 8192 worst case
#define SMEM_BYTES (SVOL * 4 + QCAP * 4)   // 98036 B

#define NTHR 1024
#define NWARP (NTHR / 32)  // 32
#define FG 7               // fill group size (rows per warp per batch)

__global__ __launch_bounds__(NTHR, 2) void deform3d_tile12_kernel(
    const float* __restrict__ X,
    const float* __restrict__ def,
    float* __restrict__ out)
{
    extern __shared__ float s[];
    int* __restrict__ q = (int*)(s + SVOL);
    __shared__ int s_qn;

    const int b  = blockIdx.z / (HH / TH);
    const int hz = blockIdx.z % (HH / TH);
    const int h0 = hz * TH;
    const int w0 = blockIdx.y * TW;
    const int d0 = blockIdx.x * TD;

    const int lane = threadIdx.x;          // 0..31 -> d
    const int ty   = threadIdx.y;          // 0..31
    const int wy   = ty & 15;              // -> w
    const int hg   = ty >> 4;              // 0/1 -> h half (8 planes each)
    const int warpId = ty;                 // 32 warps
    const int tid  = ty * 32 + lane;

    if (tid == 0) s_qn = 0;

    const float* Xb = X + (size_t)b * (NN * 2);

    const int yb = h0 - RLO;
    const int xb = w0 - RLO;
    const int zb = d0 - RLO;

    const int d = d0 + lane;
    const int w = w0 + wy;
    const int hbase = h0 + hg * (TH / 2);

    const int vox0 = ((b * HH + hbase) * WW + w) * DD + d;

    // ---- Prologue: def loads for iterations 0, 1 issued first so the
    //      fill hides their DRAM latency. ----
    float bx0, by0, bz0, bx1, by1, bz1;
    {
        const float* dp0 = def + (size_t)vox0 * 3;
        const float* dp1 = dp0 + (size_t)WD * 3;
        bx0 = __ldcs(dp0 + 0); by0 = __ldcs(dp0 + 1); bz0 = __ldcs(dp0 + 2);
        bx1 = __ldcs(dp1 + 0); by1 = __ldcs(dp1 + 1); bz1 = __ldcs(dp1 + 2);
    }

    // ---- SMEM fill: one warp per (hy,wx) row; rows batched in groups of 7
    //      so all group LDGs are outstanding before the first STS. ----
    {
        const int ezA = min(max(zb + lane, 0), DD - 1) * 2;
        const int ezB = min(max(zb + lane + 32, 0), DD - 1) * 2;

        int hy = warpId / WS;
        int wx = warpId - hy * WS;

        #pragma unroll
        for (int g = 0; g < 2; g++) {
            const int rbase = warpId + g * (NWARP * FG);
            float vA[FG], vB[FG];

            #pragma unroll
            for (int j = 0; j < FG; j++) {
                int row = rbase + j * NWARP;
                if (row < NROWS) {
                    int gy = min(max(yb + hy, 0), HH - 1);
                    int gx = min(max(xb + wx, 0), WW - 1);
                    const float* src = Xb + (size_t)(gy * WW + gx) * (DD * 2);
                    vA[j] = __ldg(src + ezA);
                    vB[j] = (lane < DS - 32) ? __ldg(src + ezB) : 0.0f;
                    wx += NWARP;
                    while (wx >= WS) { wx -= WS; hy++; }
                }
            }

            #pragma unroll
            for (int j = 0; j < FG; j++) {
                int row = rbase + j * NWARP;
                if (row < NROWS) {
                    float* dst = s + row * DS;
                    dst[lane] = vA[j];
                    if (lane < DS - 32)
                        dst[lane + 32] = vB[j];
                }
            }
        }
    }
    __syncthreads();    // also publishes s_qn = 0

    // Fast-path bounds: corner index c0 must satisfy clip-identity AND
    // in-tile:  c0 in [max(0, base), min(base + S - 2, LIM - 2)].
    const int loY = max(0, yb), rngY = min(yb + HS - 2, HH - 2) - loY;
    const int loX = max(0, xb), rngX = min(xb + WS - 2, WW - 2) - loX;
    const int loZ = max(0, zb), rngZ = min(zb + DS - 2, DD - 2) - loZ;

    const float wf = (float)w;
    const float df = (float)d;
    float hf = (float)hbase;

    int vox = vox0;
    const float* dpn = def + ((size_t)vox0 + (size_t)2 * WD) * 3;

    #pragma unroll
    for (int hh = 0; hh < TH / 2; hh++, vox += WD, hf += 1.0f) {
        // Consume the stage loaded 2 iterations ago.
        float dx, dy, dzv;
        if ((hh & 1) == 0) { dx = bx0; dy = by0; dzv = bz0; }
        else               { dx = bx1; dy = by1; dzv = bz1; }

        // Refill this stage with iteration hh+2.
        if (hh < TH / 2 - 2) {
            float nx = __ldcs(dpn + 0);
            float ny = __ldcs(dpn + 1);
            float nz = __ldcs(dpn + 2);
            if ((hh & 1) == 0) { bx0 = nx; by0 = ny; bz0 = nz; }
            else               { bx1 = nx; by1 = ny; bz1 = nz; }
            dpn += (size_t)WD * 3;
        }

        float x = wf + dx;          // def[...,0] -> W axis
        float y = hf + dy;          // def[...,1] -> H axis
        float z = df + dzv;         // def[...,2] -> D axis

        int x0 = __float2int_rd(x);
        int y0 = __float2int_rd(y);
        int z0 = __float2int_rd(z);

        bool fast = ((unsigned)(y0 - loY) <= (unsigned)rngY) &
                    ((unsigned)(x0 - loX) <= (unsigned)rngX) &
                    ((unsigned)(z0 - loZ) <= (unsigned)rngZ);

        unsigned mask = __ballot_sync(0xffffffffu, !fast);

        if (fast) {
            // clip == identity here: x1 = x0+1 etc., all taps in SMEM tile.
            float x0f = (float)x0, y0f = (float)y0, z0f = (float)z0;
            float wx1 = x - x0f, wx0 = (x0f + 1.0f) - x;
            float wy1 = y - y0f, wy0 = (y0f + 1.0f) - y;
            float wz1 = z - z0f, wz0 = (z0f + 1.0f) - z;

            int base = ((y0 - yb) * WS + (x0 - xb)) * DS + (z0 - zb);

            float p000 = s[base];
            float p001 = s[base + 1];
            float p010 = s[base + DS];
            float p011 = s[base + DS + 1];
            float p100 = s[base + WS * DS];
            float p101 = s[base + WS * DS + 1];
            float p110 = s[base + WS * DS + DS];
            float p111 = s[base + WS * DS + DS + 1];

            float res = wy0 * (wx0 * (wz0 * p000 + wz1 * p001) +
                               wx1 * (wz0 * p010 + wz1 * p011)) +
                        wy1 * (wx0 * (wz0 * p100 + wz1 * p101) +
                               wx1 * (wz0 * p110 + wz1 * p111));

            __stcs(out + vox, res);   // streaming store: keep L2 for X reuse
        } else {
            // Enqueue for the post-pass (warp-aggregated single atomic).
            int leader = __ffs(mask) - 1;
            int rank   = __popc(mask & ((1u << lane) - 1u));
            int qb;
            if (lane == leader) qb = atomicAdd(&s_qn, __popc(mask));
            qb = __shfl_sync(mask, qb, leader);
            q[qb + rank] = vox;
        }
    }

    // ---- Post-pass: drain the fallback queue with full warp efficiency.
    //      Exact reference math: clip each corner independently; weights
    //      from CLIPPED coords so out-of-range dims cancel to zero. ----
    __syncthreads();
    const int qn = s_qn;
    for (int i = tid; i < qn; i += NTHR) {
        const int vx = q[i];
        int n  = vx - ((vx >= NN) ? NN : 0);
        const float* Xq = X + (size_t)((vx >= NN) ? (NN * 2) : 0);
        int h2 = n / WD;
        int rm = n - h2 * WD;
        int w2 = rm / DD;
        int d2 = rm - w2 * DD;

        const float* dp = def + (size_t)vx * 3;
        float dx = __ldg(dp + 0);
        float dy = __ldg(dp + 1);
        float dz = __ldg(dp + 2);

        float x = (float)w2 + dx;
        float y = (float)h2 + dy;
        float z = (float)d2 + dz;

        int x0 = __float2int_rd(x), y0 = __float2int_rd(y), z0 = __float2int_rd(z);
        int x1 = x0 + 1, y1 = y0 + 1, z1 = z0 + 1;
        x0 = min(max(x0, 0), WW - 1);  x1 = min(max(x1, 0), WW - 1);
        y0 = min(max(y0, 0), HH - 1);  y1 = min(max(y1, 0), HH - 1);
        z0 = min(max(z0, 0), DD - 1);  z1 = min(max(z1, 0), DD - 1);

        float wx0 = (float)x1 - x, wx1 = x - (float)x0;
        float wy0 = (float)y1 - y, wy1 = y - (float)y0;
        float wz0 = (float)z1 - z, wz1 = z - (float)z0;

        int i00 = (y0 * WW + x0) * (DD * 2);
        int i01 = (y0 * WW + x1) * (DD * 2);
        int i10 = (y1 * WW + x0) * (DD * 2);
        int i11 = (y1 * WW + x1) * (DD * 2);
        int z0e = z0 * 2, z1e = z1 * 2;
        float p000 = __ldg(Xq + i00 + z0e), p001 = __ldg(Xq + i00 + z1e);
        float p010 = __ldg(Xq + i01 + z0e), p011 = __ldg(Xq + i01 + z1e);
        float p100 = __ldg(Xq + i10 + z0e), p101 = __ldg(Xq + i10 + z1e);
        float p110 = __ldg(Xq + i11 + z0e), p111 = __ldg(Xq + i11 + z1e);

        float res = wy0 * (wx0 * (wz0 * p000 + wz1 * p001) +
                           wx1 * (wz0 * p010 + wz1 * p011)) +
                    wy1 * (wx0 * (wz0 * p100 + wz1 * p101) +
                           wx1 * (wz0 * p110 + wz1 * p111));

        out[vx] = res;
    }
}

extern "C" void kernel_launch(void* const* d_in, const int* in_sizes, int n_in,
                              void* d_out, int out_size)
{
    const float* X   = (const float*)d_in[0];
    const float* def = (const float*)d_in[1];
    float* out = (float*)d_out;

    cudaFuncSetAttribute(deform3d_tile12_kernel,
                         cudaFuncAttributeMaxDynamicSharedMemorySize,
                         SMEM_BYTES);

    dim3 grid(DD / TD, WW / TW, BB * (HH / TH));   // (5, 12, 20) = 1200 CTAs
    dim3 block(32, 32, 1);                          // 1024 threads
    deform3d_tile12_kernel<<<grid, block, SMEM_BYTES>>>(X, def, out);
}

// round 17
// speedup vs baseline: 1.2235x; 1.0300x over previous
#include <cuda_runtime.h>

// SpatialDeformer3D via SMEM-tiled trilinear gather, v13:
//  - v12 fallback-compaction core (best ncu: 76.3us), with the queue
//    shrunk 4x via uint16 local-voxel encoding (13 bits/entry):
//    SMEM 98 -> 81.7 KB/CTA, restoring ~65KB of L1D carveout per SM.
//  - post-pass stores via __stcs (match main loop; keep L1/L2 for X).
//  - otherwise v10/v12: static 1200-CTA grid, 16x16x32 tile, +/-2 halo,
//    batched fill, depth-2 def register pipeline, __ldcs def stream,
//    fast path = base + 8 immediate-offset LDS, exact-reference fallback.
//
//   X:           (2, 160, 192, 160, 2)  float32
//   deformation: (2, 160, 192, 160, 3)  float32
//   out:         (2, 160, 192, 160, 1)  float32

#define BB 2
#define HH 160
#define WW 192
#define DD 160
#define WD (WW * DD)
#define NN (HH * WD)

#define TH 16
#define TW 16
#define TD 32
#define RLO 2              // halo below; +3 above (x1=x0+1) => extent T+5
#define HS (TH + 5)        // 21
#define WS (TW + 5)        // 21
#define DS (TD + 5)        // 37
#define NROWS (HS * WS)    // 441
#define SVOL (NROWS * DS)  // 16317 floats = 65268 B

#define QCAP (TH * TW * TD)                    // 8192 worst case
#define SMEM_BYTES (SVOL * 4 + QCAP * 2)       // 81652 B

#define NTHR 1024
#define NWARP (NTHR / 32)  // 32
#define FG 7               // fill group size (rows per warp per batch)

__global__ __launch_bounds__(NTHR, 2) void deform3d_tile13_kernel(
    const float* __restrict__ X,
    const float* __restrict__ def,
    float* __restrict__ out)
{
    extern __shared__ float s[];
    unsigned short* __restrict__ q = (unsigned short*)(s + SVOL);
    __shared__ int s_qn;

    const int b  = blockIdx.z / (HH / TH);
    const int hz = blockIdx.z % (HH / TH);
    const int h0 = hz * TH;
    const int w0 = blockIdx.y * TW;
    const int d0 = blockIdx.x * TD;

    const int lane = threadIdx.x;          // 0..31 -> d
    const int ty   = threadIdx.y;          // 0..31
    const int wy   = ty & 15;              // -> w
    const int hg   = ty >> 4;              // 0/1 -> h half (8 planes each)
    const int warpId = ty;                 // 32 warps
    const int tid  = ty * 32 + lane;

    if (tid == 0) s_qn = 0;

    const float* Xb = X + (size_t)b * (NN * 2);

    const int yb = h0 - RLO;
    const int xb = w0 - RLO;
    const int zb = d0 - RLO;

    const int d = d0 + lane;
    const int w = w0 + wy;
    const int hbase = h0 + hg * (TH / 2);

    const int vox0 = ((b * HH + hbase) * WW + w) * DD + d;

    // ---- Prologue: def loads for iterations 0, 1 issued first so the
    //      fill hides their DRAM latency. ----
    float bx0, by0, bz0, bx1, by1, bz1;
    {
        const float* dp0 = def + (size_t)vox0 * 3;
        const float* dp1 = dp0 + (size_t)WD * 3;
        bx0 = __ldcs(dp0 + 0); by0 = __ldcs(dp0 + 1); bz0 = __ldcs(dp0 + 2);
        bx1 = __ldcs(dp1 + 0); by1 = __ldcs(dp1 + 1); bz1 = __ldcs(dp1 + 2);
    }

    // ---- SMEM fill: one warp per (hy,wx) row; rows batched in groups of 7
    //      so all group LDGs are outstanding before the first STS. ----
    {
        const int ezA = min(max(zb + lane, 0), DD - 1) * 2;
        const int ezB = min(max(zb + lane + 32, 0), DD - 1) * 2;

        int hy = warpId / WS;
        int wx = warpId - hy * WS;

        #pragma unroll
        for (int g = 0; g < 2; g++) {
            const int rbase = warpId + g * (NWARP * FG);
            float vA[FG], vB[FG];

            #pragma unroll
            for (int j = 0; j < FG; j++) {
                int row = rbase + j * NWARP;
                if (row < NROWS) {
                    int gy = min(max(yb + hy, 0), HH - 1);
                    int gx = min(max(xb + wx, 0), WW - 1);
                    const float* src = Xb + (size_t)(gy * WW + gx) * (DD * 2);
                    vA[j] = __ldg(src + ezA);
                    vB[j] = (lane < DS - 32) ? __ldg(src + ezB) : 0.0f;
                    wx += NWARP;
                    while (wx >= WS) { wx -= WS; hy++; }
                }
            }

            #pragma unroll
            for (int j = 0; j < FG; j++) {
                int row = rbase + j * NWARP;
                if (row < NROWS) {
                    float* dst = s + row * DS;
                    dst[lane] = vA[j];
                    if (lane < DS - 32)
                        dst[lane + 32] = vB[j];
                }
            }
        }
    }
    __syncthreads();    // also publishes s_qn = 0

    // Fast-path bounds: corner index c0 must satisfy clip-identity AND
    // in-tile:  c0 in [max(0, base), min(base + S - 2, LIM - 2)].
    const int loY = max(0, yb), rngY = min(yb + HS - 2, HH - 2) - loY;
    const int loX = max(0, xb), rngX = min(xb + WS - 2, WW - 2) - loX;
    const int loZ = max(0, zb), rngZ = min(zb + DS - 2, DD - 2) - loZ;

    const float wf = (float)w;
    const float df = (float)d;
    float hf = (float)hbase;

    int vox = vox0;
    const float* dpn = def + ((size_t)vox0 + (size_t)2 * WD) * 3;

    #pragma unroll
    for (int hh = 0; hh < TH / 2; hh++, vox += WD, hf += 1.0f) {
        // Consume the stage loaded 2 iterations ago.
        float dx, dy, dzv;
        if ((hh & 1) == 0) { dx = bx0; dy = by0; dzv = bz0; }
        else               { dx = bx1; dy = by1; dzv = bz1; }

        // Refill this stage with iteration hh+2.
        if (hh < TH / 2 - 2) {
            float nx = __ldcs(dpn + 0);
            float ny = __ldcs(dpn + 1);
            float nz = __ldcs(dpn + 2);
            if ((hh & 1) == 0) { bx0 = nx; by0 = ny; bz0 = nz; }
            else               { bx1 = nx; by1 = ny; bz1 = nz; }
            dpn += (size_t)WD * 3;
        }

        float x = wf + dx;          // def[...,0] -> W axis
        float y = hf + dy;          // def[...,1] -> H axis
        float z = df + dzv;         // def[...,2] -> D axis

        int x0 = __float2int_rd(x);
        int y0 = __float2int_rd(y);
        int z0 = __float2int_rd(z);

        bool fast = ((unsigned)(y0 - loY) <= (unsigned)rngY) &
                    ((unsigned)(x0 - loX) <= (unsigned)rngX) &
                    ((unsigned)(z0 - loZ) <= (unsigned)rngZ);

        unsigned mask = __ballot_sync(0xffffffffu, !fast);

        if (fast) {
            // clip == identity here: x1 = x0+1 etc., all taps in SMEM tile.
            float x0f = (float)x0, y0f = (float)y0, z0f = (float)z0;
            float wx1 = x - x0f, wx0 = (x0f + 1.0f) - x;
            float wy1 = y - y0f, wy0 = (y0f + 1.0f) - y;
            float wz1 = z - z0f, wz0 = (z0f + 1.0f) - z;

            int base = ((y0 - yb) * WS + (x0 - xb)) * DS + (z0 - zb);

            float p000 = s[base];
            float p001 = s[base + 1];
            float p010 = s[base + DS];
            float p011 = s[base + DS + 1];
            float p100 = s[base + WS * DS];
            float p101 = s[base + WS * DS + 1];
            float p110 = s[base + WS * DS + DS];
            float p111 = s[base + WS * DS + DS + 1];

            float res = wy0 * (wx0 * (wz0 * p000 + wz1 * p001) +
                               wx1 * (wz0 * p010 + wz1 * p011)) +
                        wy1 * (wx0 * (wz0 * p100 + wz1 * p101) +
                               wx1 * (wz0 * p110 + wz1 * p111));

            __stcs(out + vox, res);   // streaming store: keep L2 for X reuse
        } else {
            // Enqueue local voxel id (13 bits) for the post-pass.
            int leader = __ffs(mask) - 1;
            int rank   = __popc(mask & ((1u << lane) - 1u));
            int qb;
            if (lane == leader) qb = atomicAdd(&s_qn, __popc(mask));
            qb = __shfl_sync(mask, qb, leader);
            int hp = hg * (TH / 2) + hh;                 // 0..15
            q[qb + rank] = (unsigned short)((hp << 9) | (wy << 5) | lane);
        }
    }

    // ---- Post-pass: drain the fallback queue with full warp efficiency.
    //      Exact reference math: clip each corner independently; weights
    //      from CLIPPED coords so out-of-range dims cancel to zero. ----
    __syncthreads();
    const int qn = s_qn;
    for (int i = tid; i < qn; i += NTHR) {
        const unsigned e = q[i];
        const int d2 = d0 + (int)(e & 31u);
        const int w2 = w0 + (int)((e >> 5) & 15u);
        const int h2 = h0 + (int)(e >> 9);
        const int vx = ((b * HH + h2) * WW + w2) * DD + d2;

        const float* dp = def + (size_t)vx * 3;
        float dx = __ldg(dp + 0);
        float dy = __ldg(dp + 1);
        float dz = __ldg(dp + 2);

        float x = (float)w2 + dx;
        float y = (float)h2 + dy;
        float z = (float)d2 + dz;

        int x0 = __float2int_rd(x), y0 = __float2int_rd(y), z0 = __float2int_rd(z);
        int x1 = x0 + 1, y1 = y0 + 1, z1 = z0 + 1;
        x0 = min(max(x0, 0), WW - 1);  x1 = min(max(x1, 0), WW - 1);
        y0 = min(max(y0, 0), HH - 1);  y1 = min(max(y1, 0), HH - 1);
        z0 = min(max(z0, 0), DD - 1);  z1 = min(max(z1, 0), DD - 1);

        float wx0 = (float)x1 - x, wx1 = x - (float)x0;
        float wy0 = (float)y1 - y, wy1 = y - (float)y0;
        float wz0 = (float)z1 - z, wz1 = z - (float)z0;

        int i00 = (y0 * WW + x0) * (DD * 2);
        int i01 = (y0 * WW + x1) * (DD * 2);
        int i10 = (y1 * WW + x0) * (DD * 2);
        int i11 = (y1 * WW + x1) * (DD * 2);
        int z0e = z0 * 2, z1e = z1 * 2;
        float p000 = __ldg(Xb + i00 + z0e), p001 = __ldg(Xb + i00 + z1e);
        float p010 = __ldg(Xb + i01 + z0e), p011 = __ldg(Xb + i01 + z1e);
        float p100 = __ldg(Xb + i10 + z0e), p101 = __ldg(Xb + i10 + z1e);
        float p110 = __ldg(Xb + i11 + z0e), p111 = __ldg(Xb + i11 + z1e);

        float res = wy0 * (wx0 * (wz0 * p000 + wz1 * p001) +
                           wx1 * (wz0 * p010 + wz1 * p011)) +
                    wy1 * (wx0 * (wz0 * p100 + wz1 * p101) +
                           wx1 * (wz0 * p110 + wz1 * p111));

        __stcs(out + vx, res);
    }
}

extern "C" void kernel_launch(void* const* d_in, const int* in_sizes, int n_in,
                              void* d_out, int out_size)
{
    const float* X   = (const float*)d_in[0];
    const float* def = (const float*)d_in[1];
    float* out = (float*)d_out;

    cudaFuncSetAttribute(deform3d_tile13_kernel,
                         cudaFuncAttributeMaxDynamicSharedMemorySize,
                         SMEM_BYTES);

    dim3 grid(DD / TD, WW / TW, BB * (HH / TH));   // (5, 12, 20) = 1200 CTAs
    dim3 block(32, 32, 1);                          // 1024 threads
    deform3d_tile13_kernel<<<grid, block, SMEM_BYTES>>>(X, def, out);
}